// round 5
// baseline (speedup 1.0000x reference)
#include <cuda_runtime.h>
#include <math.h>

// ---------------------------------------------------------------------------
// SOM sequential scan, round 5: barrier-free warp-specialized pipeline.
//
// 128 CTAs x 288 threads. Warp 0 = comm-only; warps 1..8 own one cell each
// (12 dims/lane, weights in registers).
//
// Global argmin per step: 128 slots (one per CTA), double-buffered rows,
// slot = (d2_bits<<32) | (cell<<14) | (step+1 & 0x3FFF).
//
// Intra-CTA handshakes are tagged smem mailboxes (NO named barriers):
//   s_bmu  : u32  ((step+1)<<10 | bcell), comm -> workers, LDS-spin wake.
//   s_pqr[c]: float4 (P, -2Q, R, tag=step+1), workers -> comm, STS.128.
// Comm iter s: issue 4 poll LDGs -> spin operands (tag s) -> spin polls
//   (tag s+1) -> redux-min pair (BMU) -> post s_bmu -> LUT + 2 FMA ->
//   redux-min pair -> relaxed STG publish (tag s+2).
// Workers step s: prefetch x_{s+2} -> spin s_bmu (tag s+1) -> update w,
//   next P/-2Q/R -> butterfly -> STS.128 (tag s+1).
// ---------------------------------------------------------------------------

#define SOM_G    128
#define SOM_TPB  288
#define SOM_DIM  384
#define SOM_NS   8192
#define SOM_EPW  12
#define SOM_CPC  8
#define SOM_MAXE 2
#define TAGMASK  0x3FFFu

__device__ unsigned long long g_slots[2][SOM_G];

static __device__ __forceinline__ unsigned long long ld_rlx(const unsigned long long* p) {
    unsigned long long v;
    asm volatile("ld.relaxed.gpu.global.b64 %0, [%1];" : "=l"(v) : "l"(p) : "memory");
    return v;
}
static __device__ __forceinline__ void st_rlx(unsigned long long* p, unsigned long long v) {
    asm volatile("st.relaxed.gpu.global.b64 [%0], %1;" :: "l"(p), "l"(v) : "memory");
}
static __device__ __forceinline__ unsigned lds_vol_u32(const unsigned* p) {
    unsigned v;
    unsigned a = (unsigned)__cvta_generic_to_shared(p);
    asm volatile("ld.volatile.shared.u32 %0, [%1];" : "=r"(v) : "r"(a) : "memory");
    return v;
}
static __device__ __forceinline__ void sts_vol_u32(unsigned* p, unsigned v) {
    unsigned a = (unsigned)__cvta_generic_to_shared(p);
    asm volatile("st.volatile.shared.u32 [%0], %1;" :: "r"(a), "r"(v) : "memory");
}
static __device__ __forceinline__ float4 lds_vol_f4(const float4* p) {
    float4 v;
    unsigned a = (unsigned)__cvta_generic_to_shared(p);
    asm volatile("ld.volatile.shared.v4.f32 {%0,%1,%2,%3}, [%4];"
                 : "=f"(v.x), "=f"(v.y), "=f"(v.z), "=f"(v.w) : "r"(a) : "memory");
    return v;
}
static __device__ __forceinline__ void sts_vol_f4(float4* p, float x, float y,
                                                  float z, float w) {
    unsigned a = (unsigned)__cvta_generic_to_shared(p);
    asm volatile("st.volatile.shared.v4.f32 [%0], {%1,%2,%3,%4};"
                 :: "r"(a), "f"(x), "f"(y), "f"(z), "f"(w) : "memory");
}
static __device__ __forceinline__ unsigned long long umin64(unsigned long long a,
                                                            unsigned long long b) {
    return a < b ? a : b;
}
// warp-wide min of packed (d2<<32 | cell<<14 | tag); tags identical across lanes
static __device__ __forceinline__ unsigned long long warp_min64(unsigned long long v) {
    unsigned hi  = (unsigned)(v >> 32);
    unsigned mhi = __reduce_min_sync(0xffffffffu, hi);
    unsigned lo  = (hi == mhi) ? (unsigned)v : 0xffffffffu;
    unsigned mlo = __reduce_min_sync(0xffffffffu, lo);
    return ((unsigned long long)mhi << 32) | mlo;
}

static __device__ __forceinline__ int read_epochs(const int* p) {
    int e = p[0];
    if (e < 1 || e > SOM_MAXE) {
        float fe = __int_as_float(e);
        if (fe >= 1.0f && fe <= (float)SOM_MAXE) e = (int)fe;
        else e = 1;
    }
    return e;
}

__global__ void som_init_slots() {
    int i = threadIdx.x;
    if (i < 2 * SOM_G) ((unsigned long long*)g_slots)[i] = 0ull;
}

__global__ void __launch_bounds__(SOM_TPB, 1)
som_kernel(const float* __restrict__ X,   // [8192, 384]
           const float* __restrict__ W0,  // [32, 32, 384]
           const int* __restrict__ pep,
           float* __restrict__ out)       // [32, 32, 384]
{
    __shared__ float lut[63 * 64];
    __shared__ __align__(16) float4 s_pqr[SOM_CPC];  // (P, -2Q, R, tag)
    __shared__ unsigned s_bmu;                       // ((step+1)<<10)|bcell

    const int tid  = threadIdx.x;
    const int wid  = tid >> 5;
    const int lane = tid & 31;
    const int cta  = blockIdx.x;
    const int S    = read_epochs(pep) * SOM_NS;

    if (tid == 0) s_bmu = 0u;
    for (int i = tid; i < 63 * 64; i += SOM_TPB) {
        float fx = (float)((i >> 6) - 31);
        float fy = (float)((i & 63) - 31);
        lut[i] = 0.1f * expf(-0.5f * sqrtf(fx * fx + fy * fy));
    }

    // ---------------- worker state + prologue ----------------
    float w[SOM_EPW], v[SOM_EPW], xn[SOM_EPW];
    int cell = 0, cgx = 0, cgy = 0;
    if (wid > 0) {
        cell = cta * SOM_CPC + (wid - 1);
        cgx = cell >> 5; cgy = cell & 31;
        const float* wr = W0 + (size_t)cell * SOM_DIM + lane;
#pragma unroll
        for (int k = 0; k < SOM_EPW; k++) w[k] = wr[k * 32];
        const float* x0 = X + lane;
        const float* x1 = X + (size_t)SOM_DIM + lane;
        float p = 0.f, q = 0.f, r = 0.f;
#pragma unroll
        for (int k = 0; k < SOM_EPW; k++) {
            float a0 = x0[k * 32];
            float a1 = x1[k * 32];
            float vv = a0 - w[k];
            float uu = a1 - w[k];
            v[k]  = vv;
            xn[k] = a1;
            r = fmaf(vv, vv, r);
            q = fmaf(uu, vv, q);
            p = fmaf(uu, uu, p);
        }
#pragma unroll
        for (int o = 16; o; o >>= 1) {
            p += __shfl_xor_sync(0xffffffffu, p, o);
            q += __shfl_xor_sync(0xffffffffu, q, o);
            r += __shfl_xor_sync(0xffffffffu, r, o);
        }
        if (lane == 0)
            sts_vol_f4(&s_pqr[wid - 1], p, -2.0f * q, r, __uint_as_float(0u));
    }
    __syncthreads();

    if (wid == 0) {
        // ================= COMM WARP =================
        // publish step-0 mins (d2_0 == R), slot tag 1, row 0
        {
            unsigned long long pk = 0xFFFFFFFFFFFFFFFFull;
            if (lane < SOM_CPC) {
                float r0 = s_pqr[lane].z;
                unsigned pcell = (unsigned)(cta * SOM_CPC + lane);
                pk = ((unsigned long long)__float_as_uint(r0) << 32)
                   | (pcell << 14) | 1u;
            }
            unsigned long long m = warp_min64(pk);
            if (lane == 0) st_rlx(&g_slots[0][cta], m);
        }

        const unsigned pc = (unsigned)(cta * SOM_CPC + (lane & 7));
        const int pgx = (int)(pc >> 5), pgy = (int)(pc & 31);

        for (int s = 0; s < S; s++) {
            const bool more = (s + 1 < S);

            // 1) issue global poll loads FIRST (overlap with operand spin)
            const unsigned tag = (unsigned)(s + 1) & TAGMASK;
            const unsigned long long* base = &g_slots[s & 1][0];
            const unsigned long long *q0 = base + lane,      *q1 = base + lane + 32,
                                     *q2 = base + lane + 64, *q3 = base + lane + 96;
            unsigned long long v0 = ld_rlx(q0), v1 = ld_rlx(q1),
                               v2 = ld_rlx(q2), v3 = ld_rlx(q3);

            // 2) fetch publish operands (workers' step s-1 output, tag s)
            float Pp = 0.f, Qp = 0.f, Rp = 0.f;
            if (more) {
                if (lane < SOM_CPC) {
                    float4 t;
                    do { t = lds_vol_f4(&s_pqr[lane]); }
                    while (__float_as_uint(t.w) != (unsigned)s);
                    Pp = t.x; Qp = t.y; Rp = t.z;
                }
                __syncwarp();
            }

            // 3) finish global poll for step s
            for (;;) {
                bool b0 = ((unsigned)v0 & TAGMASK) != tag;
                bool b1 = ((unsigned)v1 & TAGMASK) != tag;
                bool b2 = ((unsigned)v2 & TAGMASK) != tag;
                bool b3 = ((unsigned)v3 & TAGMASK) != tag;
                if (!(b0 | b1 | b2 | b3)) break;
                if (b0) v0 = ld_rlx(q0);
                if (b1) v1 = ld_rlx(q1);
                if (b2) v2 = ld_rlx(q2);
                if (b3) v3 = ld_rlx(q3);
            }
            __syncwarp();
            unsigned long long gm =
                warp_min64(umin64(umin64(v0, v1), umin64(v2, v3)));
            const unsigned bcell = ((unsigned)gm >> 14) & 0x3FFu;

            // 4) wake workers IMMEDIATELY (before publish tail)
            if (lane == 0)
                sts_vol_u32(&s_bmu, ((unsigned)(s + 1) << 10) | bcell);

            // 5) publish step s+1
            if (more) {
                unsigned long long pk = 0xFFFFFFFFFFFFFFFFull;
                if (lane < SOM_CPC) {
                    float a = lut[(pgx - (int)(bcell >> 5) + 31) * 64 +
                                  (pgy - (int)(bcell & 31) + 31)];
                    float d2 = fmaxf(fmaf(a, fmaf(a, Rp, Qp), Pp), 0.0f);
                    pk = ((unsigned long long)__float_as_uint(d2) << 32)
                       | (pc << 14) | ((unsigned)(s + 2) & TAGMASK);
                }
                unsigned long long pm = warp_min64(pk);
                if (lane == 0) st_rlx(&g_slots[(s + 1) & 1][cta], pm);
            }
        }
    } else {
        // ================= WORKER WARPS =================
        for (int s = 0; s < S; s++) {
            // prefetch x_{s+2} while waiting for BMU(s)
            float xf[SOM_EPW];
            {
                const float* xr =
                    X + (size_t)((s + 2) & (SOM_NS - 1)) * SOM_DIM + lane;
#pragma unroll
                for (int k = 0; k < SOM_EPW; k++) xf[k] = xr[k * 32];
            }

            // spin for BMU(s): word tag (s+1)<<10
            const unsigned want = (unsigned)(s + 1) << 10;
            unsigned bv;
            do { bv = lds_vol_u32(&s_bmu); } while ((bv & 0xFFFFFC00u) != want);
            const unsigned bcell = bv & 0x3FFu;
            const float a = lut[(cgx - (int)(bcell >> 5) + 31) * 64 +
                                (cgy - (int)(bcell & 31) + 31)];

            float p = 0.f, q = 0.f, r = 0.f;
#pragma unroll
            for (int k = 0; k < SOM_EPW; k++) {
                float wn = fmaf(a, v[k], w[k]);   // w^(s+1)
                float u  = xn[k] - wn;            // next v
                float z  = xf[k] - wn;
                r = fmaf(u, u, r);
                q = fmaf(z, u, q);
                p = fmaf(z, z, p);
                w[k]  = wn;
                v[k]  = u;
                xn[k] = xf[k];
            }
            if (s + 2 < S) {
#pragma unroll
                for (int o = 16; o; o >>= 1) {
                    p += __shfl_xor_sync(0xffffffffu, p, o);
                    q += __shfl_xor_sync(0xffffffffu, q, o);
                    r += __shfl_xor_sync(0xffffffffu, r, o);
                }
                if (lane == 0)
                    sts_vol_f4(&s_pqr[wid - 1], p, -2.0f * q, r,
                               __uint_as_float((unsigned)(s + 1)));
            }
        }

        // write final weights
        float* orow = out + (size_t)cell * SOM_DIM + lane;
#pragma unroll
        for (int k = 0; k < SOM_EPW; k++) orow[k * 32] = w[k];
    }
}

extern "C" void kernel_launch(void* const* d_in, const int* in_sizes, int n_in,
                              void* d_out, int out_size) {
    const float* X  = (const float*)d_in[0];
    const float* W0 = (const float*)d_in[1];
    const int* pep  = (const int*)d_in[3];
    (void)in_sizes; (void)n_in; (void)out_size;

    som_init_slots<<<1, 256>>>();
    som_kernel<<<SOM_G, SOM_TPB>>>(X, W0, pep, (float*)d_out);
}